// round 15
// baseline (speedup 1.0000x reference)
#include <cuda_runtime.h>
#include <cuda_fp16.h>
#include <math.h>

// ---------------- problem constants ----------------
#define BATCH   4
#define SEQ_Q   3072
#define SEQ_KV  1036
#define D_E     1024
#define D_C     768
#define N_HEADS 8
#define D_HEAD  128

#define MQ (BATCH * SEQ_Q)    // 12288
#define MKV (BATCH * SEQ_KV)  // 4144
#define SKV_PAD 1088

// ---------------- scratch ----------------
__device__ __half g_hx[(size_t)MQ * D_E];
__device__ __half g_hy[(size_t)MKV * D_C];
__device__ __half g_hWq[(size_t)D_E * D_E];
__device__ __half g_hWk[(size_t)D_E * D_C];
__device__ __half g_hWv[(size_t)D_E * D_C];
__device__ __half g_hWo[(size_t)D_E * D_E];
__device__ __half g_Q[(size_t)MQ * D_E];
__device__ __half g_K[(size_t)MKV * D_E];
__device__ __half g_V[(size_t)MKV * D_E];
__device__ __half g_Vt[(size_t)BATCH * N_HEADS * D_HEAD * SKV_PAD];
__device__ __half g_O[(size_t)MQ * D_E];

// ---------------- helpers ----------------
__device__ __forceinline__ unsigned packh2(float lo, float hi) {
    __half2 h = __floats2half2_rn(lo, hi);
    return *reinterpret_cast<unsigned*>(&h);
}

__device__ __forceinline__ void mma_f16(float d[4], const unsigned a[4], const unsigned b[2]) {
    asm volatile(
        "mma.sync.aligned.m16n8k16.row.col.f32.f16.f16.f32 "
        "{%0,%1,%2,%3}, {%4,%5,%6,%7}, {%8,%9}, {%0,%1,%2,%3};\n"
        : "+f"(d[0]), "+f"(d[1]), "+f"(d[2]), "+f"(d[3])
        : "r"(a[0]), "r"(a[1]), "r"(a[2]), "r"(a[3]),
          "r"(b[0]), "r"(b[1]));
}

__device__ __forceinline__ void ldsm_x4(unsigned& r0, unsigned& r1, unsigned& r2, unsigned& r3,
                                        unsigned saddr) {
    asm volatile("ldmatrix.sync.aligned.m8n8.x4.shared.b16 {%0,%1,%2,%3}, [%4];"
                 : "=r"(r0), "=r"(r1), "=r"(r2), "=r"(r3) : "r"(saddr));
}

// base-2 exp on the MUFU pipe (scores arrive pre-scaled by log2(e))
__device__ __forceinline__ float fexp2(float x) {
    x = fmaxf(x, -126.0f);
    float r;
    asm("ex2.approx.f32 %0, %1;" : "=f"(r) : "f"(x));
    return r;
}

__device__ __forceinline__ void cp_async16(unsigned dst, const void* src, int src_bytes) {
    asm volatile("cp.async.cg.shared.global [%0], [%1], 16, %2;"
                 :: "r"(dst), "l"(src), "r"(src_bytes));
}
__device__ __forceinline__ void cp_commit() { asm volatile("cp.async.commit_group;"); }
template<int N>
__device__ __forceinline__ void cp_wait() { asm volatile("cp.async.wait_group %0;" :: "n"(N)); }

// ============================================================
// fp32 -> fp16 conversion: all 6 tensors in ONE launch (segmented)
// ============================================================
#define C_NX 3145728
#define C_N0 (C_NX + 795648)
#define C_N1 (C_N0 + 262144)
#define C_N2 (C_N1 + 196608)
#define C_N3 (C_N2 + 196608)
#define C_N4 (C_N3 + 262144)

__global__ __launch_bounds__(256) void cvt_all(
    const float* __restrict__ x,  const float* __restrict__ y,
    const float* __restrict__ wq, const float* __restrict__ wk,
    const float* __restrict__ wv, const float* __restrict__ wo,
    __half* hx, __half* hy, __half* hwq, __half* hwk, __half* hwv, __half* hwo)
{
    int i = blockIdx.x * 256 + threadIdx.x;
    const float* src; __half* dst; int j;
    if      (i < C_NX) { src = x;  dst = hx;  j = i; }
    else if (i < C_N0) { src = y;  dst = hy;  j = i - C_NX; }
    else if (i < C_N1) { src = wq; dst = hwq; j = i - C_N0; }
    else if (i < C_N2) { src = wk; dst = hwk; j = i - C_N1; }
    else if (i < C_N3) { src = wv; dst = hwv; j = i - C_N2; }
    else if (i < C_N4) { src = wo; dst = hwo; j = i - C_N3; }
    else return;
    float4 v = *reinterpret_cast<const float4*>(src + (size_t)j * 4);
    __half2* o = reinterpret_cast<__half2*>(dst + (size_t)j * 4);
    o[0] = __floats2half2_rn(v.x, v.y);
    o[1] = __floats2half2_rn(v.z, v.w);
}

// ============================================================
// V transpose: g_V [MKV][D_E] -> g_Vt [B*H][128][SKV_PAD]
// ============================================================
__global__ __launch_bounds__(256) void transpose_v(const __half* __restrict__ V,
                                                   __half* __restrict__ Vt)
{
    __shared__ __half t[32][33];
    const int tx = threadIdx.x;
    const int ty = threadIdx.y;
    const int kv0 = blockIdx.x * 32;
    const int d0  = blockIdx.y * 32;
    const int bh  = blockIdx.z;
    const int b   = bh >> 3, h = bh & 7;

    #pragma unroll
    for (int j = 0; j < 4; j++) {
        int kvL = ty * 4 + j;
        int kv  = kv0 + kvL;
        __half v = __float2half(0.0f);
        if (kv < SEQ_KV)
            v = V[(size_t)(b * SEQ_KV + kv) * D_E + h * D_HEAD + d0 + tx];
        t[kvL][tx] = v;
    }
    __syncthreads();
    #pragma unroll
    for (int j = 0; j < 4; j++) {
        int dL = ty * 4 + j;
        Vt[((size_t)bh * D_HEAD + d0 + dL) * SKV_PAD + kv0 + tx] = t[tx][dL];
    }
}

// ============================================================
// fp16 tensor-core GEMM, up to 3 independent segments per launch.
// block 128x128x64(half), 3-stage cp.async, 1 sync/iter,
// ldmatrix frags + B-fragment double buffering. smem 96KB, 2 CTAs/SM
// ============================================================
struct Seg {
    const __half* A;
    const __half* W;
    const float*  bias;
    void*         C;
    int M, K, ohalf;
    float oscale;
};

#define GSTG 16384u
#define GEMM_SMEM (6 * 16384)

__global__ __launch_bounds__(256, 2) void gemm_f16(
    Seg s0, Seg s1, Seg s2, int nx, int N)
{
    extern __shared__ __half gsm[];

    const int tid  = threadIdx.x;
    const int lane = tid & 31;
    const int wid  = tid >> 5;
    const int wm   = wid >> 2;
    const int wn   = wid & 3;
    const int r4   = lane >> 2;
    const int c    = lane & 3;
    const int m0   = blockIdx.y * 128;

    int bx = blockIdx.x;
    Seg s = (bx < nx) ? s0 : ((bx < 2 * nx) ? s1 : s2);
    bx = (bx >= nx) ? (bx >= 2 * nx ? bx - 2 * nx : bx - nx) : bx;
    const int n0 = bx * 128;
    if (m0 >= s.M) return;

    const __half* A = s.A;
    const __half* W = s.W;
    const int M = s.M, K = s.K;

    const unsigned sa_s = (unsigned)__cvta_generic_to_shared(gsm);
    const unsigned sb_s = sa_s + 3 * GSTG;

    float acc[4][4][4];
    #pragma unroll
    for (int i = 0; i < 4; i++)
        #pragma unroll
        for (int j = 0; j < 4; j++)
            #pragma unroll
            for (int e = 0; e < 4; e++) acc[i][j][e] = 0.0f;

    auto issue = [&](int ch, int buf) {
        const int k0 = ch * 64;
        #pragma unroll
        for (int i = 0; i < 4; i++) {
            int u = tid + i * 256;
            int row = u >> 3, g = u & 7;
            int gr = m0 + row;
            int sz = (gr < M) ? 16 : 0;
            int grc = (gr < M) ? gr : (M - 1);
            cp_async16(sa_s + (unsigned)buf * GSTG + (unsigned)(row * 128 + ((g ^ (row & 7)) << 4)),
                       A + (size_t)grc * K + k0 + g * 8, sz);
        }
        #pragma unroll
        for (int i = 0; i < 4; i++) {
            int u = tid + i * 256;
            int row = u >> 3, g = u & 7;
            cp_async16(sb_s + (unsigned)buf * GSTG + (unsigned)(row * 128 + ((g ^ (row & 7)) << 4)),
                       W + (size_t)(n0 + row) * K + k0 + g * 8, 16);
        }
        cp_commit();
    };

    const int arow = (lane & 7) + (lane & 8);
    const int ahib = (lane & 16) ? 1 : 0;
    const int brow = (lane & 7) + ((lane & 16) ? 8 : 0);
    const int bhib = (lane & 8) ? 1 : 0;
    const int l7   = lane & 7;

    const int nk = K >> 6;
    issue(0, 0);
    if (nk > 1) issue(1, 1);

    for (int i = 0; i < nk; i++) {
        const int buf = i % 3;
        if (i + 1 < nk) cp_wait<1>(); else cp_wait<0>();
        __syncthreads();

        const unsigned aT = sa_s + (unsigned)buf * GSTG;
        const unsigned bT = sb_s + (unsigned)buf * GSTG;
        const unsigned bRow0 = bT + (unsigned)((wn * 32 + brow) * 128);
        const unsigned bRow1 = bT + (unsigned)((wn * 32 + 16 + brow) * 128);

        unsigned bf[2][4][2];
        {
            const unsigned gb = (unsigned)((bhib ^ l7) << 4);
            ldsm_x4(bf[0][0][0], bf[0][0][1], bf[0][1][0], bf[0][1][1], bRow0 + gb);
            ldsm_x4(bf[0][2][0], bf[0][2][1], bf[0][3][0], bf[0][3][1], bRow1 + gb);
        }

        #pragma unroll
        for (int kt = 0; kt < 4; kt++) {
            const int cur = kt & 1;
            if (kt < 3) {
                const unsigned gb = (unsigned)(((2 * (kt + 1) + bhib) ^ l7) << 4);
                ldsm_x4(bf[cur ^ 1][0][0], bf[cur ^ 1][0][1],
                        bf[cur ^ 1][1][0], bf[cur ^ 1][1][1], bRow0 + gb);
                ldsm_x4(bf[cur ^ 1][2][0], bf[cur ^ 1][2][1],
                        bf[cur ^ 1][3][0], bf[cur ^ 1][3][1], bRow1 + gb);
            }
            unsigned af[4][4];
            const unsigned ga = (unsigned)(((2 * kt + ahib) ^ l7) << 4);
            #pragma unroll
            for (int mi = 0; mi < 4; mi++)
                ldsm_x4(af[mi][0], af[mi][1], af[mi][2], af[mi][3],
                        aT + (unsigned)((wm * 64 + mi * 16 + arow) * 128) + ga);
            #pragma unroll
            for (int mi = 0; mi < 4; mi++)
                #pragma unroll
                for (int ni = 0; ni < 4; ni++)
                    mma_f16(acc[mi][ni], af[mi], bf[cur][ni]);
        }

        if (i + 2 < nk) issue(i + 2, (i + 2) % 3);
    }

    // ---- epilogue ----
    #pragma unroll
    for (int mi = 0; mi < 4; mi++) {
        int row1 = m0 + wm * 64 + mi * 16 + r4;
        int row2 = row1 + 8;
        #pragma unroll
        for (int ni = 0; ni < 4; ni++) {
            int colg = n0 + wn * 32 + ni * 8 + c * 2;
            float b0 = s.bias[colg], b1 = s.bias[colg + 1];
            float v00 = acc[mi][ni][0] + b0, v01 = acc[mi][ni][1] + b1;
            float v10 = acc[mi][ni][2] + b0, v11 = acc[mi][ni][3] + b1;
            if (s.ohalf) {
                __half* C = (__half*)s.C;
                if (row1 < M)
                    *reinterpret_cast<unsigned*>(C + (size_t)row1 * N + colg) =
                        packh2(s.oscale * v00, s.oscale * v01);
                if (row2 < M)
                    *reinterpret_cast<unsigned*>(C + (size_t)row2 * N + colg) =
                        packh2(s.oscale * v10, s.oscale * v11);
            } else {
                float* C = (float*)s.C;
                if (row1 < M)
                    *reinterpret_cast<float2*>(C + (size_t)row1 * N + colg) = make_float2(v00, v01);
                if (row2 < M)
                    *reinterpret_cast<float2*>(C + (size_t)row2 * N + colg) = make_float2(v10, v11);
            }
        }
    }
}

// ============================================================
// fa7: fp16 flash attention, base-2 softmax on MUFU pipe.
// Q arrives pre-scaled by (1/sqrt(d))*log2(e): scores in log2 domain.
// Otherwise identical to fa6 (4-stage cp.async, 1 sync/iter,
// K-frag double buffering, OOB mask hoisted).
// ============================================================
#define NCHUNK 17
#define KTB 16384u
#define VTB 16384u
#define FA7_SMEM_BYTES (4 * (16384 + 16384))

__global__ __launch_bounds__(256, 1) void fa7_f16(
    const __half* __restrict__ Q, const __half* __restrict__ K,
    const __half* __restrict__ Vt, __half* __restrict__ O)
{
    extern __shared__ unsigned sm4[];

    const int tid  = threadIdx.x;
    const int lane = tid & 31;
    const int wid  = tid >> 5;
    const int r4   = lane >> 2;
    const int c    = lane & 3;
    const int q0   = blockIdx.x * 128;
    const int h    = blockIdx.y;
    const int b    = blockIdx.z;

    const unsigned sbase = (unsigned)__cvta_generic_to_shared(sm4);
    const unsigned k_s = sbase;
    const unsigned v_s = sbase + 4 * KTB;

    const __half* kb  = K + ((size_t)(b * SEQ_KV)) * D_E + h * D_HEAD;
    const __half* vtb = Vt + ((size_t)(b * N_HEADS + h)) * D_HEAD * SKV_PAD;

    const int lrow = (lane & 7) + ((lane & 16) ? 8 : 0);
    const int kbit = (lane & 8) ? 1 : 0;
    const int lx   = lane & 7;

    unsigned qf[8][4];
    {
        const unsigned* qb = reinterpret_cast<const unsigned*>(
            Q + ((size_t)(b * SEQ_Q + q0 + wid * 16)) * D_E + h * D_HEAD);
        #pragma unroll
        for (int kt = 0; kt < 8; kt++) {
            qf[kt][0] = __ldg(qb + (size_t)r4 * 512 + kt * 8 + c);
            qf[kt][1] = __ldg(qb + (size_t)(r4 + 8) * 512 + kt * 8 + c);
            qf[kt][2] = __ldg(qb + (size_t)r4 * 512 + kt * 8 + c + 4);
            qf[kt][3] = __ldg(qb + (size_t)(r4 + 8) * 512 + kt * 8 + c + 4);
        }
    }

    float oacc[16][4];
    #pragma unroll
    for (int nt = 0; nt < 16; nt++)
        #pragma unroll
        for (int e = 0; e < 4; e++) oacc[nt][e] = 0.0f;

    float row_m0 = -1e30f, row_m1 = -1e30f;
    float row_l0 = 0.0f,   row_l1 = 0.0f;

    auto issue_chunk = [&](int t, int buf) {
        const int kv0 = t * 64;
        #pragma unroll
        for (int i = 0; i < 4; i++) {
            int u = tid + i * 256;
            int kv = u >> 4, g = u & 15;
            int kvg = kv0 + kv;
            int sz = (kvg < SEQ_KV) ? 16 : 0;
            int kvc = (kvg < SEQ_KV) ? kvg : (SEQ_KV - 1);
            cp_async16(k_s + (unsigned)buf * KTB + (unsigned)(kv * 256 + ((g ^ (kv & 7)) << 4)),
                       kb + (size_t)kvc * D_E + g * 8, sz);
        }
        #pragma unroll
        for (int i = 0; i < 4; i++) {
            int u = tid + i * 256;
            int d = u >> 3, g = u & 7;
            cp_async16(v_s + (unsigned)buf * VTB + (unsigned)(d * 128 + ((g ^ (d & 7)) << 4)),
                       vtb + (size_t)d * SKV_PAD + kv0 + g * 8, 16);
        }
        cp_commit();
    };

    issue_chunk(0, 0);
    issue_chunk(1, 1);
    issue_chunk(2, 2);

    for (int t = 0; t < NCHUNK; t++) {
        const int kv0 = t * 64;
        const int buf = t & 3;

        if (t + 3 <= NCHUNK) cp_wait<2>();
        else if (t + 2 == NCHUNK) cp_wait<1>();
        else cp_wait<0>();
        __syncthreads();

        const unsigned kT = k_s + (unsigned)buf * KTB + lrow * 256;
        const unsigned vT = v_s + (unsigned)buf * VTB + lrow * 128;

        // ---- S = Q @ K^T (log2-domain scores), K-frags double-buffered ----
        float sacc[8][4];
        #pragma unroll
        for (int ni = 0; ni < 8; ni++)
            #pragma unroll
            for (int e = 0; e < 4; e++) sacc[ni][e] = 0.0f;

        unsigned kf[2][4][4];
        {
            const unsigned g0 = (unsigned)(((kbit) ^ lx) << 4);
            #pragma unroll
            for (int np = 0; np < 4; np++)
                ldsm_x4(kf[0][np][0], kf[0][np][1], kf[0][np][2], kf[0][np][3],
                        kT + np * 4096 + g0);
        }
        #pragma unroll
        for (int kt = 0; kt < 8; kt++) {
            const int cur = kt & 1;
            if (kt < 7) {
                const unsigned gn = (unsigned)(((2 * (kt + 1) + kbit) ^ lx) << 4);
                #pragma unroll
                for (int np = 0; np < 4; np++)
                    ldsm_x4(kf[cur ^ 1][np][0], kf[cur ^ 1][np][1],
                            kf[cur ^ 1][np][2], kf[cur ^ 1][np][3],
                            kT + np * 4096 + gn);
            }
            #pragma unroll
            for (int np = 0; np < 4; np++) {
                unsigned bfA[2] = {kf[cur][np][0], kf[cur][np][1]};
                unsigned bfB[2] = {kf[cur][np][2], kf[cur][np][3]};
                mma_f16(sacc[2 * np],     qf[kt], bfA);
                mma_f16(sacc[2 * np + 1], qf[kt], bfB);
            }
        }

        // ---- base-2 softmax (MUFU ex2), OOB mask on final chunk only ----
        float mx0 = -1e30f, mx1 = -1e30f;
        if (t == NCHUNK - 1) {
            #pragma unroll
            for (int ni = 0; ni < 8; ni++) {
                int colg = kv0 + ni * 8 + c * 2;
                if (colg >= SEQ_KV) {
                    sacc[ni][0] = -1e30f; sacc[ni][1] = -1e30f;
                    sacc[ni][2] = -1e30f; sacc[ni][3] = -1e30f;
                }
                mx0 = fmaxf(mx0, fmaxf(sacc[ni][0], sacc[ni][1]));
                mx1 = fmaxf(mx1, fmaxf(sacc[ni][2], sacc[ni][3]));
            }
        } else {
            #pragma unroll
            for (int ni = 0; ni < 8; ni++) {
                mx0 = fmaxf(mx0, fmaxf(sacc[ni][0], sacc[ni][1]));
                mx1 = fmaxf(mx1, fmaxf(sacc[ni][2], sacc[ni][3]));
            }
        }
        mx0 = fmaxf(mx0, __shfl_xor_sync(0xffffffffu, mx0, 1));
        mx0 = fmaxf(mx0, __shfl_xor_sync(0xffffffffu, mx0, 2));
        mx1 = fmaxf(mx1, __shfl_xor_sync(0xffffffffu, mx1, 1));
        mx1 = fmaxf(mx1, __shfl_xor_sync(0xffffffffu, mx1, 2));

        float mnew0 = fmaxf(row_m0, mx0);
        float mnew1 = fmaxf(row_m1, mx1);
        float sc0 = fexp2(row_m0 - mnew0);
        float sc1 = fexp2(row_m1 - mnew1);
        row_m0 = mnew0; row_m1 = mnew1;

        float sum0 = 0.f, sum1 = 0.f;
        #pragma unroll
        for (int ni = 0; ni < 8; ni++) {
            sacc[ni][0] = fexp2(sacc[ni][0] - mnew0);
            sacc[ni][1] = fexp2(sacc[ni][1] - mnew0);
            sacc[ni][2] = fexp2(sacc[ni][2] - mnew1);
            sacc[ni][3] = fexp2(sacc[ni][3] - mnew1);
            sum0 += sacc[ni][0] + sacc[ni][1];
            sum1 += sacc[ni][2] + sacc[ni][3];
        }
        sum0 += __shfl_xor_sync(0xffffffffu, sum0, 1);
        sum0 += __shfl_xor_sync(0xffffffffu, sum0, 2);
        sum1 += __shfl_xor_sync(0xffffffffu, sum1, 1);
        sum1 += __shfl_xor_sync(0xffffffffu, sum1, 2);
        row_l0 = row_l0 * sc0 + sum0;
        row_l1 = row_l1 * sc1 + sum1;

        // skip rescale when max unchanged (exp2(0)==1 exactly; x1.0 is exact)
        if (!(sc0 == 1.0f && sc1 == 1.0f)) {
            #pragma unroll
            for (int nt = 0; nt < 16; nt++) {
                oacc[nt][0] *= sc0; oacc[nt][1] *= sc0;
                oacc[nt][2] *= sc1; oacc[nt][3] *= sc1;
            }
        }

        // ---- O += P @ V ----
        #pragma unroll
        for (int kt = 0; kt < 4; kt++) {
            unsigned pa[4];
            pa[0] = packh2(sacc[2 * kt][0],     sacc[2 * kt][1]);
            pa[1] = packh2(sacc[2 * kt][2],     sacc[2 * kt][3]);
            pa[2] = packh2(sacc[2 * kt + 1][0], sacc[2 * kt + 1][1]);
            pa[3] = packh2(sacc[2 * kt + 1][2], sacc[2 * kt + 1][3]);

            const unsigned goff = (unsigned)(((2 * kt + kbit) ^ lx) << 4);
            #pragma unroll
            for (int np = 0; np < 8; np++) {
                unsigned b0, b1, b2, b3;
                ldsm_x4(b0, b1, b2, b3, vT + np * 2048 + goff);
                unsigned bfA[2] = {b0, b1};
                unsigned bfB[2] = {b2, b3};
                mma_f16(oacc[2 * np],     pa, bfA);
                mma_f16(oacc[2 * np + 1], pa, bfB);
            }
        }

        if (t + 3 < NCHUNK) issue_chunk(t + 3, (t + 3) & 3);
    }

    float inv0 = 1.0f / row_l0;
    float inv1 = 1.0f / row_l1;
    __half* ob = O + ((size_t)(b * SEQ_Q + q0 + wid * 16 + r4)) * D_E + h * D_HEAD;
    #pragma unroll
    for (int nt = 0; nt < 16; nt++) {
        int colg = nt * 8 + c * 2;
        *reinterpret_cast<unsigned*>(ob + colg) =
            packh2(oacc[nt][0] * inv0, oacc[nt][1] * inv0);
        *reinterpret_cast<unsigned*>(ob + (size_t)8 * D_E + colg) =
            packh2(oacc[nt][2] * inv1, oacc[nt][3] * inv1);
    }
}

// ============================================================
// launch
// ============================================================
extern "C" void kernel_launch(void* const* d_in, const int* in_sizes, int n_in,
                              void* d_out, int out_size)
{
    const float* x  = (const float*)d_in[0];
    const float* y  = (const float*)d_in[1];
    const float* Wq = (const float*)d_in[2];
    const float* bq = (const float*)d_in[3];
    const float* Wk = (const float*)d_in[4];
    const float* bk = (const float*)d_in[5];
    const float* Wv = (const float*)d_in[6];
    const float* bv = (const float*)d_in[7];
    const float* Wo = (const float*)d_in[8];
    const float* bo = (const float*)d_in[9];
    float* out = (float*)d_out;

    __half *hx, *hy, *hWq, *hWk, *hWv, *hWo, *pQ, *pK, *pV, *pVt, *pO;
    cudaGetSymbolAddress((void**)&hx,  g_hx);
    cudaGetSymbolAddress((void**)&hy,  g_hy);
    cudaGetSymbolAddress((void**)&hWq, g_hWq);
    cudaGetSymbolAddress((void**)&hWk, g_hWk);
    cudaGetSymbolAddress((void**)&hWv, g_hWv);
    cudaGetSymbolAddress((void**)&hWo, g_hWo);
    cudaGetSymbolAddress((void**)&pQ,  g_Q);
    cudaGetSymbolAddress((void**)&pK,  g_K);
    cudaGetSymbolAddress((void**)&pV,  g_V);
    cudaGetSymbolAddress((void**)&pVt, g_Vt);
    cudaGetSymbolAddress((void**)&pO,  g_O);

    // (1/sqrt(128)) * log2(e): softmax runs in base-2 domain
    const float qscale = 0.08838834764831845f * 1.4426950408889634f;

    // launch 0: all fp32->fp16 conversions
    cvt_all<<<(C_N4 + 255) / 256, 256>>>(x, y, Wq, Wk, Wv, Wo,
                                         hx, hy, hWq, hWk, hWv, hWo);

    cudaFuncSetAttribute(gemm_f16, cudaFuncAttributeMaxDynamicSharedMemorySize, GEMM_SMEM);

    // launch 1: Q + K + V projections in one launch (3 segments)
    Seg sq = { hx, hWq, bq, pQ, MQ,  D_E, 1, qscale };
    Seg sk = { hy, hWk, bk, pK, MKV, D_C, 1, 1.0f };
    Seg sv = { hy, hWv, bv, pV, MKV, D_C, 1, 1.0f };
    gemm_f16<<<dim3(24, (MQ + 127) / 128), 256, GEMM_SMEM>>>(sq, sk, sv, 8, D_E);

    // launch 2: V transpose
    transpose_v<<<dim3(SKV_PAD / 32, D_HEAD / 32, BATCH * N_HEADS), dim3(32, 8)>>>(pV, pVt);

    // launch 3: attention
    cudaFuncSetAttribute(fa7_f16, cudaFuncAttributeMaxDynamicSharedMemorySize, FA7_SMEM_BYTES);
    fa7_f16<<<dim3(SEQ_Q / 128, N_HEADS, BATCH), 256, FA7_SMEM_BYTES>>>(pQ, pK, pVt, pO);

    // launch 4: output projection -> d_out (fp32)
    Seg so = { pO, hWo, bo, out, MQ, D_E, 0, 1.0f };
    gemm_f16<<<dim3(8, (MQ + 127) / 128), 256, GEMM_SMEM>>>(so, so, so, 8, D_E);
}

// round 16
// speedup vs baseline: 1.0758x; 1.0758x over previous
#include <cuda_runtime.h>
#include <cuda_fp16.h>
#include <math.h>

// ---------------- problem constants ----------------
#define BATCH   4
#define SEQ_Q   3072
#define SEQ_KV  1036
#define D_E     1024
#define D_C     768
#define N_HEADS 8
#define D_HEAD  128

#define MQ (BATCH * SEQ_Q)    // 12288
#define MKV (BATCH * SEQ_KV)  // 4144
#define SKV_PAD 1088

// ---------------- scratch ----------------
__device__ __half g_hx[(size_t)MQ * D_E];
__device__ __half g_hy[(size_t)MKV * D_C];
__device__ __half g_hWq[(size_t)D_E * D_E];
__device__ __half g_hWk[(size_t)D_E * D_C];
__device__ __half g_hWv[(size_t)D_E * D_C];
__device__ __half g_hWo[(size_t)D_E * D_E];
__device__ __half g_Q[(size_t)MQ * D_E];
__device__ __half g_K[(size_t)MKV * D_E];
__device__ __half g_V[(size_t)MKV * D_E];
__device__ __half g_Vt[(size_t)BATCH * N_HEADS * D_HEAD * SKV_PAD];
__device__ __half g_O[(size_t)MQ * D_E];

// ---------------- helpers ----------------
__device__ __forceinline__ unsigned packh2(float lo, float hi) {
    __half2 h = __floats2half2_rn(lo, hi);
    return *reinterpret_cast<unsigned*>(&h);
}

__device__ __forceinline__ void mma_f16(float d[4], const unsigned a[4], const unsigned b[2]) {
    asm volatile(
        "mma.sync.aligned.m16n8k16.row.col.f32.f16.f16.f32 "
        "{%0,%1,%2,%3}, {%4,%5,%6,%7}, {%8,%9}, {%0,%1,%2,%3};\n"
        : "+f"(d[0]), "+f"(d[1]), "+f"(d[2]), "+f"(d[3])
        : "r"(a[0]), "r"(a[1]), "r"(a[2]), "r"(a[3]),
          "r"(b[0]), "r"(b[1]));
}

__device__ __forceinline__ void ldsm_x4(unsigned& r0, unsigned& r1, unsigned& r2, unsigned& r3,
                                        unsigned saddr) {
    asm volatile("ldmatrix.sync.aligned.m8n8.x4.shared.b16 {%0,%1,%2,%3}, [%4];"
                 : "=r"(r0), "=r"(r1), "=r"(r2), "=r"(r3) : "r"(saddr));
}

// base-2 exp on the MUFU pipe (scores arrive pre-scaled by log2(e))
__device__ __forceinline__ float fexp2(float x) {
    x = fmaxf(x, -126.0f);
    float r;
    asm("ex2.approx.f32 %0, %1;" : "=f"(r) : "f"(x));
    return r;
}

__device__ __forceinline__ void cp_async16(unsigned dst, const void* src, int src_bytes) {
    asm volatile("cp.async.cg.shared.global [%0], [%1], 16, %2;"
                 :: "r"(dst), "l"(src), "r"(src_bytes));
}
__device__ __forceinline__ void cp_commit() { asm volatile("cp.async.commit_group;"); }
template<int N>
__device__ __forceinline__ void cp_wait() { asm volatile("cp.async.wait_group %0;" :: "n"(N)); }

// ============================================================
// fp32 -> fp16 conversion: all 6 tensors in ONE launch (segmented)
// ============================================================
#define C_NX 3145728
#define C_N0 (C_NX + 795648)
#define C_N1 (C_N0 + 262144)
#define C_N2 (C_N1 + 196608)
#define C_N3 (C_N2 + 196608)
#define C_N4 (C_N3 + 262144)

__global__ __launch_bounds__(256) void cvt_all(
    const float* __restrict__ x,  const float* __restrict__ y,
    const float* __restrict__ wq, const float* __restrict__ wk,
    const float* __restrict__ wv, const float* __restrict__ wo,
    __half* hx, __half* hy, __half* hwq, __half* hwk, __half* hwv, __half* hwo)
{
    int i = blockIdx.x * 256 + threadIdx.x;
    const float* src; __half* dst; int j;
    if      (i < C_NX) { src = x;  dst = hx;  j = i; }
    else if (i < C_N0) { src = y;  dst = hy;  j = i - C_NX; }
    else if (i < C_N1) { src = wq; dst = hwq; j = i - C_N0; }
    else if (i < C_N2) { src = wk; dst = hwk; j = i - C_N1; }
    else if (i < C_N3) { src = wv; dst = hwv; j = i - C_N2; }
    else if (i < C_N4) { src = wo; dst = hwo; j = i - C_N3; }
    else return;
    float4 v = *reinterpret_cast<const float4*>(src + (size_t)j * 4);
    __half2* o = reinterpret_cast<__half2*>(dst + (size_t)j * 4);
    o[0] = __floats2half2_rn(v.x, v.y);
    o[1] = __floats2half2_rn(v.z, v.w);
}

// ============================================================
// V transpose: g_V [MKV][D_E] -> g_Vt [B*H][128][SKV_PAD]
// ============================================================
__global__ __launch_bounds__(256) void transpose_v(const __half* __restrict__ V,
                                                   __half* __restrict__ Vt)
{
    __shared__ __half t[32][33];
    const int tx = threadIdx.x;
    const int ty = threadIdx.y;
    const int kv0 = blockIdx.x * 32;
    const int d0  = blockIdx.y * 32;
    const int bh  = blockIdx.z;
    const int b   = bh >> 3, h = bh & 7;

    #pragma unroll
    for (int j = 0; j < 4; j++) {
        int kvL = ty * 4 + j;
        int kv  = kv0 + kvL;
        __half v = __float2half(0.0f);
        if (kv < SEQ_KV)
            v = V[(size_t)(b * SEQ_KV + kv) * D_E + h * D_HEAD + d0 + tx];
        t[kvL][tx] = v;
    }
    __syncthreads();
    #pragma unroll
    for (int j = 0; j < 4; j++) {
        int dL = ty * 4 + j;
        Vt[((size_t)bh * D_HEAD + d0 + dL) * SKV_PAD + kv0 + tx] = t[tx][dL];
    }
}

// ============================================================
// fp16 tensor-core GEMM, up to 3 independent segments per launch.
// block 128x128x64(half), 3-stage cp.async, 1 sync/iter,
// ldmatrix frags + B-fragment double buffering. smem 96KB, 2 CTAs/SM
// ============================================================
struct Seg {
    const __half* A;
    const __half* W;
    const float*  bias;
    void*         C;
    int M, K, ohalf;
    float oscale;
};

#define GSTG 16384u
#define GEMM_SMEM (6 * 16384)

__global__ __launch_bounds__(256, 2) void gemm_f16(
    Seg s0, Seg s1, Seg s2, int nx, int N)
{
    extern __shared__ __half gsm[];

    const int tid  = threadIdx.x;
    const int lane = tid & 31;
    const int wid  = tid >> 5;
    const int wm   = wid >> 2;
    const int wn   = wid & 3;
    const int r4   = lane >> 2;
    const int c    = lane & 3;
    const int m0   = blockIdx.y * 128;

    int bx = blockIdx.x;
    Seg s = (bx < nx) ? s0 : ((bx < 2 * nx) ? s1 : s2);
    bx = (bx >= nx) ? (bx >= 2 * nx ? bx - 2 * nx : bx - nx) : bx;
    const int n0 = bx * 128;
    if (m0 >= s.M) return;

    const __half* A = s.A;
    const __half* W = s.W;
    const int M = s.M, K = s.K;

    const unsigned sa_s = (unsigned)__cvta_generic_to_shared(gsm);
    const unsigned sb_s = sa_s + 3 * GSTG;

    float acc[4][4][4];
    #pragma unroll
    for (int i = 0; i < 4; i++)
        #pragma unroll
        for (int j = 0; j < 4; j++)
            #pragma unroll
            for (int e = 0; e < 4; e++) acc[i][j][e] = 0.0f;

    auto issue = [&](int ch, int buf) {
        const int k0 = ch * 64;
        #pragma unroll
        for (int i = 0; i < 4; i++) {
            int u = tid + i * 256;
            int row = u >> 3, g = u & 7;
            int gr = m0 + row;
            int sz = (gr < M) ? 16 : 0;
            int grc = (gr < M) ? gr : (M - 1);
            cp_async16(sa_s + (unsigned)buf * GSTG + (unsigned)(row * 128 + ((g ^ (row & 7)) << 4)),
                       A + (size_t)grc * K + k0 + g * 8, sz);
        }
        #pragma unroll
        for (int i = 0; i < 4; i++) {
            int u = tid + i * 256;
            int row = u >> 3, g = u & 7;
            cp_async16(sb_s + (unsigned)buf * GSTG + (unsigned)(row * 128 + ((g ^ (row & 7)) << 4)),
                       W + (size_t)(n0 + row) * K + k0 + g * 8, 16);
        }
        cp_commit();
    };

    const int arow = (lane & 7) + (lane & 8);
    const int ahib = (lane & 16) ? 1 : 0;
    const int brow = (lane & 7) + ((lane & 16) ? 8 : 0);
    const int bhib = (lane & 8) ? 1 : 0;
    const int l7   = lane & 7;

    const int nk = K >> 6;
    issue(0, 0);
    if (nk > 1) issue(1, 1);

    for (int i = 0; i < nk; i++) {
        const int buf = i % 3;
        if (i + 1 < nk) cp_wait<1>(); else cp_wait<0>();
        __syncthreads();

        const unsigned aT = sa_s + (unsigned)buf * GSTG;
        const unsigned bT = sb_s + (unsigned)buf * GSTG;
        const unsigned bRow0 = bT + (unsigned)((wn * 32 + brow) * 128);
        const unsigned bRow1 = bT + (unsigned)((wn * 32 + 16 + brow) * 128);

        unsigned bf[2][4][2];
        {
            const unsigned gb = (unsigned)((bhib ^ l7) << 4);
            ldsm_x4(bf[0][0][0], bf[0][0][1], bf[0][1][0], bf[0][1][1], bRow0 + gb);
            ldsm_x4(bf[0][2][0], bf[0][2][1], bf[0][3][0], bf[0][3][1], bRow1 + gb);
        }

        #pragma unroll
        for (int kt = 0; kt < 4; kt++) {
            const int cur = kt & 1;
            if (kt < 3) {
                const unsigned gb = (unsigned)(((2 * (kt + 1) + bhib) ^ l7) << 4);
                ldsm_x4(bf[cur ^ 1][0][0], bf[cur ^ 1][0][1],
                        bf[cur ^ 1][1][0], bf[cur ^ 1][1][1], bRow0 + gb);
                ldsm_x4(bf[cur ^ 1][2][0], bf[cur ^ 1][2][1],
                        bf[cur ^ 1][3][0], bf[cur ^ 1][3][1], bRow1 + gb);
            }
            unsigned af[4][4];
            const unsigned ga = (unsigned)(((2 * kt + ahib) ^ l7) << 4);
            #pragma unroll
            for (int mi = 0; mi < 4; mi++)
                ldsm_x4(af[mi][0], af[mi][1], af[mi][2], af[mi][3],
                        aT + (unsigned)((wm * 64 + mi * 16 + arow) * 128) + ga);
            #pragma unroll
            for (int mi = 0; mi < 4; mi++)
                #pragma unroll
                for (int ni = 0; ni < 4; ni++)
                    mma_f16(acc[mi][ni], af[mi], bf[cur][ni]);
        }

        if (i + 2 < nk) issue(i + 2, (i + 2) % 3);
    }

    // ---- epilogue ----
    #pragma unroll
    for (int mi = 0; mi < 4; mi++) {
        int row1 = m0 + wm * 64 + mi * 16 + r4;
        int row2 = row1 + 8;
        #pragma unroll
        for (int ni = 0; ni < 4; ni++) {
            int colg = n0 + wn * 32 + ni * 8 + c * 2;
            float b0 = s.bias[colg], b1 = s.bias[colg + 1];
            float v00 = acc[mi][ni][0] + b0, v01 = acc[mi][ni][1] + b1;
            float v10 = acc[mi][ni][2] + b0, v11 = acc[mi][ni][3] + b1;
            if (s.ohalf) {
                __half* C = (__half*)s.C;
                if (row1 < M)
                    *reinterpret_cast<unsigned*>(C + (size_t)row1 * N + colg) =
                        packh2(s.oscale * v00, s.oscale * v01);
                if (row2 < M)
                    *reinterpret_cast<unsigned*>(C + (size_t)row2 * N + colg) =
                        packh2(s.oscale * v10, s.oscale * v11);
            } else {
                float* C = (float*)s.C;
                if (row1 < M)
                    *reinterpret_cast<float2*>(C + (size_t)row1 * N + colg) = make_float2(v00, v01);
                if (row2 < M)
                    *reinterpret_cast<float2*>(C + (size_t)row2 * N + colg) = make_float2(v10, v11);
            }
        }
    }
}

// ============================================================
// fa8: fp16 flash attention, 2 CTAs/SM for cross-CTA overlap.
// CTA: 128 threads (4 warps), 64 q-rows, kv chunks of 64.
// 3-stage cp.async (96KB smem/CTA), base-2 MUFU softmax,
// K-frag double buffering, OOB mask hoisted to final chunk.
// ============================================================
#define NCHUNK 17
#define KTB 16384u
#define VTB 16384u
#define FA8_SMEM_BYTES (3 * (16384 + 16384))

__global__ __launch_bounds__(128, 2) void fa8_f16(
    const __half* __restrict__ Q, const __half* __restrict__ K,
    const __half* __restrict__ Vt, __half* __restrict__ O)
{
    extern __shared__ unsigned sm4[];

    const int tid  = threadIdx.x;
    const int lane = tid & 31;
    const int wid  = tid >> 5;      // 0..3
    const int r4   = lane >> 2;
    const int c    = lane & 3;
    const int q0   = blockIdx.x * 64;
    const int h    = blockIdx.y;
    const int b    = blockIdx.z;

    const unsigned sbase = (unsigned)__cvta_generic_to_shared(sm4);
    const unsigned k_s = sbase;                // [3][KTB]
    const unsigned v_s = sbase + 3 * KTB;      // [3][VTB]

    const __half* kb  = K + ((size_t)(b * SEQ_KV)) * D_E + h * D_HEAD;
    const __half* vtb = Vt + ((size_t)(b * N_HEADS + h)) * D_HEAD * SKV_PAD;

    const int lrow = (lane & 7) + ((lane & 16) ? 8 : 0);
    const int kbit = (lane & 8) ? 1 : 0;
    const int lx   = lane & 7;

    unsigned qf[8][4];
    {
        const unsigned* qb = reinterpret_cast<const unsigned*>(
            Q + ((size_t)(b * SEQ_Q + q0 + wid * 16)) * D_E + h * D_HEAD);
        #pragma unroll
        for (int kt = 0; kt < 8; kt++) {
            qf[kt][0] = __ldg(qb + (size_t)r4 * 512 + kt * 8 + c);
            qf[kt][1] = __ldg(qb + (size_t)(r4 + 8) * 512 + kt * 8 + c);
            qf[kt][2] = __ldg(qb + (size_t)r4 * 512 + kt * 8 + c + 4);
            qf[kt][3] = __ldg(qb + (size_t)(r4 + 8) * 512 + kt * 8 + c + 4);
        }
    }

    float oacc[16][4];
    #pragma unroll
    for (int nt = 0; nt < 16; nt++)
        #pragma unroll
        for (int e = 0; e < 4; e++) oacc[nt][e] = 0.0f;

    float row_m0 = -1e30f, row_m1 = -1e30f;
    float row_l0 = 0.0f,   row_l1 = 0.0f;

    // 128-thread staging: K tile 1024 uint4 slots, V tile 1024 slots
    auto issue_chunk = [&](int t, int buf) {
        const int kv0 = t * 64;
        #pragma unroll
        for (int i = 0; i < 8; i++) {
            int u = tid + i * 128;
            int kv = u >> 4, g = u & 15;
            int kvg = kv0 + kv;
            int sz = (kvg < SEQ_KV) ? 16 : 0;
            int kvc = (kvg < SEQ_KV) ? kvg : (SEQ_KV - 1);
            cp_async16(k_s + (unsigned)buf * KTB + (unsigned)(kv * 256 + ((g ^ (kv & 7)) << 4)),
                       kb + (size_t)kvc * D_E + g * 8, sz);
        }
        #pragma unroll
        for (int i = 0; i < 8; i++) {
            int u = tid + i * 128;
            int d = u >> 3, g = u & 7;
            cp_async16(v_s + (unsigned)buf * VTB + (unsigned)(d * 128 + ((g ^ (d & 7)) << 4)),
                       vtb + (size_t)d * SKV_PAD + kv0 + g * 8, 16);
        }
        cp_commit();
    };

    issue_chunk(0, 0);
    issue_chunk(1, 1);

    for (int t = 0; t < NCHUNK; t++) {
        const int kv0 = t * 64;
        const int buf = t % 3;

        if (t + 1 < NCHUNK) cp_wait<1>(); else cp_wait<0>();
        __syncthreads();

        const unsigned kT = k_s + (unsigned)buf * KTB + lrow * 256;
        const unsigned vT = v_s + (unsigned)buf * VTB + lrow * 128;

        // ---- S = Q @ K^T (log2-domain), K-frags double-buffered ----
        float sacc[8][4];
        #pragma unroll
        for (int ni = 0; ni < 8; ni++)
            #pragma unroll
            for (int e = 0; e < 4; e++) sacc[ni][e] = 0.0f;

        unsigned kf[2][4][4];
        {
            const unsigned g0 = (unsigned)(((kbit) ^ lx) << 4);
            #pragma unroll
            for (int np = 0; np < 4; np++)
                ldsm_x4(kf[0][np][0], kf[0][np][1], kf[0][np][2], kf[0][np][3],
                        kT + np * 4096 + g0);
        }
        #pragma unroll
        for (int kt = 0; kt < 8; kt++) {
            const int cur = kt & 1;
            if (kt < 7) {
                const unsigned gn = (unsigned)(((2 * (kt + 1) + kbit) ^ lx) << 4);
                #pragma unroll
                for (int np = 0; np < 4; np++)
                    ldsm_x4(kf[cur ^ 1][np][0], kf[cur ^ 1][np][1],
                            kf[cur ^ 1][np][2], kf[cur ^ 1][np][3],
                            kT + np * 4096 + gn);
            }
            #pragma unroll
            for (int np = 0; np < 4; np++) {
                unsigned bfA[2] = {kf[cur][np][0], kf[cur][np][1]};
                unsigned bfB[2] = {kf[cur][np][2], kf[cur][np][3]};
                mma_f16(sacc[2 * np],     qf[kt], bfA);
                mma_f16(sacc[2 * np + 1], qf[kt], bfB);
            }
        }

        // ---- base-2 softmax (MUFU ex2), OOB mask on final chunk only ----
        float mx0 = -1e30f, mx1 = -1e30f;
        if (t == NCHUNK - 1) {
            #pragma unroll
            for (int ni = 0; ni < 8; ni++) {
                int colg = kv0 + ni * 8 + c * 2;
                if (colg >= SEQ_KV) {
                    sacc[ni][0] = -1e30f; sacc[ni][1] = -1e30f;
                    sacc[ni][2] = -1e30f; sacc[ni][3] = -1e30f;
                }
                mx0 = fmaxf(mx0, fmaxf(sacc[ni][0], sacc[ni][1]));
                mx1 = fmaxf(mx1, fmaxf(sacc[ni][2], sacc[ni][3]));
            }
        } else {
            #pragma unroll
            for (int ni = 0; ni < 8; ni++) {
                mx0 = fmaxf(mx0, fmaxf(sacc[ni][0], sacc[ni][1]));
                mx1 = fmaxf(mx1, fmaxf(sacc[ni][2], sacc[ni][3]));
            }
        }
        mx0 = fmaxf(mx0, __shfl_xor_sync(0xffffffffu, mx0, 1));
        mx0 = fmaxf(mx0, __shfl_xor_sync(0xffffffffu, mx0, 2));
        mx1 = fmaxf(mx1, __shfl_xor_sync(0xffffffffu, mx1, 1));
        mx1 = fmaxf(mx1, __shfl_xor_sync(0xffffffffu, mx1, 2));

        float mnew0 = fmaxf(row_m0, mx0);
        float mnew1 = fmaxf(row_m1, mx1);
        float sc0 = fexp2(row_m0 - mnew0);
        float sc1 = fexp2(row_m1 - mnew1);
        row_m0 = mnew0; row_m1 = mnew1;

        float sum0 = 0.f, sum1 = 0.f;
        #pragma unroll
        for (int ni = 0; ni < 8; ni++) {
            sacc[ni][0] = fexp2(sacc[ni][0] - mnew0);
            sacc[ni][1] = fexp2(sacc[ni][1] - mnew0);
            sacc[ni][2] = fexp2(sacc[ni][2] - mnew1);
            sacc[ni][3] = fexp2(sacc[ni][3] - mnew1);
            sum0 += sacc[ni][0] + sacc[ni][1];
            sum1 += sacc[ni][2] + sacc[ni][3];
        }
        sum0 += __shfl_xor_sync(0xffffffffu, sum0, 1);
        sum0 += __shfl_xor_sync(0xffffffffu, sum0, 2);
        sum1 += __shfl_xor_sync(0xffffffffu, sum1, 1);
        sum1 += __shfl_xor_sync(0xffffffffu, sum1, 2);
        row_l0 = row_l0 * sc0 + sum0;
        row_l1 = row_l1 * sc1 + sum1;

        if (!(sc0 == 1.0f && sc1 == 1.0f)) {
            #pragma unroll
            for (int nt = 0; nt < 16; nt++) {
                oacc[nt][0] *= sc0; oacc[nt][1] *= sc0;
                oacc[nt][2] *= sc1; oacc[nt][3] *= sc1;
            }
        }

        // ---- O += P @ V ----
        #pragma unroll
        for (int kt = 0; kt < 4; kt++) {
            unsigned pa[4];
            pa[0] = packh2(sacc[2 * kt][0],     sacc[2 * kt][1]);
            pa[1] = packh2(sacc[2 * kt][2],     sacc[2 * kt][3]);
            pa[2] = packh2(sacc[2 * kt + 1][0], sacc[2 * kt + 1][1]);
            pa[3] = packh2(sacc[2 * kt + 1][2], sacc[2 * kt + 1][3]);

            const unsigned goff = (unsigned)(((2 * kt + kbit) ^ lx) << 4);
            #pragma unroll
            for (int np = 0; np < 8; np++) {
                unsigned b0, b1, b2, b3;
                ldsm_x4(b0, b1, b2, b3, vT + np * 2048 + goff);
                unsigned bfA[2] = {b0, b1};
                unsigned bfB[2] = {b2, b3};
                mma_f16(oacc[2 * np],     pa, bfA);
                mma_f16(oacc[2 * np + 1], pa, bfB);
            }
        }

        if (t + 2 < NCHUNK) issue_chunk(t + 2, (t + 2) % 3);
    }

    float inv0 = 1.0f / row_l0;
    float inv1 = 1.0f / row_l1;
    __half* ob = O + ((size_t)(b * SEQ_Q + q0 + wid * 16 + r4)) * D_E + h * D_HEAD;
    #pragma unroll
    for (int nt = 0; nt < 16; nt++) {
        int colg = nt * 8 + c * 2;
        *reinterpret_cast<unsigned*>(ob + colg) =
            packh2(oacc[nt][0] * inv0, oacc[nt][1] * inv0);
        *reinterpret_cast<unsigned*>(ob + (size_t)8 * D_E + colg) =
            packh2(oacc[nt][2] * inv1, oacc[nt][3] * inv1);
    }
}

// ============================================================
// launch
// ============================================================
extern "C" void kernel_launch(void* const* d_in, const int* in_sizes, int n_in,
                              void* d_out, int out_size)
{
    const float* x  = (const float*)d_in[0];
    const float* y  = (const float*)d_in[1];
    const float* Wq = (const float*)d_in[2];
    const float* bq = (const float*)d_in[3];
    const float* Wk = (const float*)d_in[4];
    const float* bk = (const float*)d_in[5];
    const float* Wv = (const float*)d_in[6];
    const float* bv = (const float*)d_in[7];
    const float* Wo = (const float*)d_in[8];
    const float* bo = (const float*)d_in[9];
    float* out = (float*)d_out;

    __half *hx, *hy, *hWq, *hWk, *hWv, *hWo, *pQ, *pK, *pV, *pVt, *pO;
    cudaGetSymbolAddress((void**)&hx,  g_hx);
    cudaGetSymbolAddress((void**)&hy,  g_hy);
    cudaGetSymbolAddress((void**)&hWq, g_hWq);
    cudaGetSymbolAddress((void**)&hWk, g_hWk);
    cudaGetSymbolAddress((void**)&hWv, g_hWv);
    cudaGetSymbolAddress((void**)&hWo, g_hWo);
    cudaGetSymbolAddress((void**)&pQ,  g_Q);
    cudaGetSymbolAddress((void**)&pK,  g_K);
    cudaGetSymbolAddress((void**)&pV,  g_V);
    cudaGetSymbolAddress((void**)&pVt, g_Vt);
    cudaGetSymbolAddress((void**)&pO,  g_O);

    // (1/sqrt(128)) * log2(e): softmax runs in base-2 domain
    const float qscale = 0.08838834764831845f * 1.4426950408889634f;

    // launch 0: all fp32->fp16 conversions
    cvt_all<<<(C_N4 + 255) / 256, 256>>>(x, y, Wq, Wk, Wv, Wo,
                                         hx, hy, hWq, hWk, hWv, hWo);

    cudaFuncSetAttribute(gemm_f16, cudaFuncAttributeMaxDynamicSharedMemorySize, GEMM_SMEM);

    // launch 1: Q + K + V projections in one launch (3 segments)
    Seg sq = { hx, hWq, bq, pQ, MQ,  D_E, 1, qscale };
    Seg sk = { hy, hWk, bk, pK, MKV, D_C, 1, 1.0f };
    Seg sv = { hy, hWv, bv, pV, MKV, D_C, 1, 1.0f };
    gemm_f16<<<dim3(24, (MQ + 127) / 128), 256, GEMM_SMEM>>>(sq, sk, sv, 8, D_E);

    // launch 2: V transpose
    transpose_v<<<dim3(SKV_PAD / 32, D_HEAD / 32, BATCH * N_HEADS), dim3(32, 8)>>>(pV, pVt);

    // launch 3: attention (2 CTAs/SM)
    cudaFuncSetAttribute(fa8_f16, cudaFuncAttributeMaxDynamicSharedMemorySize, FA8_SMEM_BYTES);
    fa8_f16<<<dim3(SEQ_Q / 64, N_HEADS, BATCH), 128, FA8_SMEM_BYTES>>>(pQ, pK, pVt, pO);

    // launch 4: output projection -> d_out (fp32)
    Seg so = { pO, hWo, bo, out, MQ, D_E, 0, 1.0f };
    gemm_f16<<<dim3(8, (MQ + 127) / 128), 256, GEMM_SMEM>>>(so, so, so, 8, D_E);
}

// round 17
// speedup vs baseline: 1.0848x; 1.0084x over previous
#include <cuda_runtime.h>
#include <cuda_fp16.h>
#include <math.h>

// ---------------- problem constants ----------------
#define BATCH   4
#define SEQ_Q   3072
#define SEQ_KV  1036
#define D_E     1024
#define D_C     768
#define N_HEADS 8
#define D_HEAD  128

#define MQ (BATCH * SEQ_Q)    // 12288
#define MKV (BATCH * SEQ_KV)  // 4144
#define SKV_PAD 1088

// ---------------- scratch ----------------
__device__ __half g_hx[(size_t)MQ * D_E];
__device__ __half g_hy[(size_t)MKV * D_C];
__device__ __half g_hWq[(size_t)D_E * D_E];
__device__ __half g_hWk[(size_t)D_E * D_C];
__device__ __half g_hWv[(size_t)D_E * D_C];
__device__ __half g_hWo[(size_t)D_E * D_E];
__device__ __half g_Q[(size_t)MQ * D_E];
__device__ __half g_K[(size_t)MKV * D_E];
__device__ __half g_Vt[(size_t)BATCH * N_HEADS * D_HEAD * SKV_PAD];  // zero-init padding
__device__ __half g_O[(size_t)MQ * D_E];

// ---------------- helpers ----------------
__device__ __forceinline__ unsigned packh2(float lo, float hi) {
    __half2 h = __floats2half2_rn(lo, hi);
    return *reinterpret_cast<unsigned*>(&h);
}

__device__ __forceinline__ void mma_f16(float d[4], const unsigned a[4], const unsigned b[2]) {
    asm volatile(
        "mma.sync.aligned.m16n8k16.row.col.f32.f16.f16.f32 "
        "{%0,%1,%2,%3}, {%4,%5,%6,%7}, {%8,%9}, {%0,%1,%2,%3};\n"
        : "+f"(d[0]), "+f"(d[1]), "+f"(d[2]), "+f"(d[3])
        : "r"(a[0]), "r"(a[1]), "r"(a[2]), "r"(a[3]),
          "r"(b[0]), "r"(b[1]));
}

__device__ __forceinline__ void ldsm_x4(unsigned& r0, unsigned& r1, unsigned& r2, unsigned& r3,
                                        unsigned saddr) {
    asm volatile("ldmatrix.sync.aligned.m8n8.x4.shared.b16 {%0,%1,%2,%3}, [%4];"
                 : "=r"(r0), "=r"(r1), "=r"(r2), "=r"(r3) : "r"(saddr));
}

// base-2 exp on the MUFU pipe (scores arrive pre-scaled by log2(e))
__device__ __forceinline__ float fexp2(float x) {
    x = fmaxf(x, -126.0f);
    float r;
    asm("ex2.approx.f32 %0, %1;" : "=f"(r) : "f"(x));
    return r;
}

__device__ __forceinline__ void cp_async16(unsigned dst, const void* src, int src_bytes) {
    asm volatile("cp.async.cg.shared.global [%0], [%1], 16, %2;"
                 :: "r"(dst), "l"(src), "r"(src_bytes));
}
__device__ __forceinline__ void cp_commit() { asm volatile("cp.async.commit_group;"); }
template<int N>
__device__ __forceinline__ void cp_wait() { asm volatile("cp.async.wait_group %0;" :: "n"(N)); }

// ============================================================
// fp32 -> fp16 conversion: all 6 tensors in ONE launch (segmented)
// ============================================================
#define C_NX 3145728
#define C_N0 (C_NX + 795648)
#define C_N1 (C_N0 + 262144)
#define C_N2 (C_N1 + 196608)
#define C_N3 (C_N2 + 196608)
#define C_N4 (C_N3 + 262144)

__global__ __launch_bounds__(256) void cvt_all(
    const float* __restrict__ x,  const float* __restrict__ y,
    const float* __restrict__ wq, const float* __restrict__ wk,
    const float* __restrict__ wv, const float* __restrict__ wo,
    __half* hx, __half* hy, __half* hwq, __half* hwk, __half* hwv, __half* hwo)
{
    int i = blockIdx.x * 256 + threadIdx.x;
    const float* src; __half* dst; int j;
    if      (i < C_NX) { src = x;  dst = hx;  j = i; }
    else if (i < C_N0) { src = y;  dst = hy;  j = i - C_NX; }
    else if (i < C_N1) { src = wq; dst = hwq; j = i - C_N0; }
    else if (i < C_N2) { src = wk; dst = hwk; j = i - C_N1; }
    else if (i < C_N3) { src = wv; dst = hwv; j = i - C_N2; }
    else if (i < C_N4) { src = wo; dst = hwo; j = i - C_N3; }
    else return;
    float4 v = *reinterpret_cast<const float4*>(src + (size_t)j * 4);
    __half2* o = reinterpret_cast<__half2*>(dst + (size_t)j * 4);
    o[0] = __floats2half2_rn(v.x, v.y);
    o[1] = __floats2half2_rn(v.z, v.w);
}

// ============================================================
// fp16 tensor-core GEMM, up to 3 independent segments per launch.
// block 128x128x64(half), 3-stage cp.async, 1 sync/iter,
// ldmatrix frags + B-fragment double buffering. smem 96KB, 2 CTAs/SM.
// otrans segment: epilogue stores transposed into g_Vt [bh][d][kv].
// ============================================================
struct Seg {
    const __half* A;
    const __half* W;
    const float*  bias;
    void*         C;
    int M, K, ohalf, otrans;
    float oscale;
};

#define GSTG 16384u
#define GEMM_SMEM (6 * 16384)

__global__ __launch_bounds__(256, 2) void gemm_f16(
    Seg s0, Seg s1, Seg s2, int nx, int N)
{
    extern __shared__ __half gsm[];

    const int tid  = threadIdx.x;
    const int lane = tid & 31;
    const int wid  = tid >> 5;
    const int wm   = wid >> 2;
    const int wn   = wid & 3;
    const int r4   = lane >> 2;
    const int c    = lane & 3;
    const int m0   = blockIdx.y * 128;

    int bx = blockIdx.x;
    Seg s = (bx < nx) ? s0 : ((bx < 2 * nx) ? s1 : s2);
    bx = (bx >= nx) ? (bx >= 2 * nx ? bx - 2 * nx : bx - nx) : bx;
    const int n0 = bx * 128;
    if (m0 >= s.M) return;

    const __half* A = s.A;
    const __half* W = s.W;
    const int M = s.M, K = s.K;

    const unsigned sa_s = (unsigned)__cvta_generic_to_shared(gsm);
    const unsigned sb_s = sa_s + 3 * GSTG;

    float acc[4][4][4];
    #pragma unroll
    for (int i = 0; i < 4; i++)
        #pragma unroll
        for (int j = 0; j < 4; j++)
            #pragma unroll
            for (int e = 0; e < 4; e++) acc[i][j][e] = 0.0f;

    auto issue = [&](int ch, int buf) {
        const int k0 = ch * 64;
        #pragma unroll
        for (int i = 0; i < 4; i++) {
            int u = tid + i * 256;
            int row = u >> 3, g = u & 7;
            int gr = m0 + row;
            int sz = (gr < M) ? 16 : 0;
            int grc = (gr < M) ? gr : (M - 1);
            cp_async16(sa_s + (unsigned)buf * GSTG + (unsigned)(row * 128 + ((g ^ (row & 7)) << 4)),
                       A + (size_t)grc * K + k0 + g * 8, sz);
        }
        #pragma unroll
        for (int i = 0; i < 4; i++) {
            int u = tid + i * 256;
            int row = u >> 3, g = u & 7;
            cp_async16(sb_s + (unsigned)buf * GSTG + (unsigned)(row * 128 + ((g ^ (row & 7)) << 4)),
                       W + (size_t)(n0 + row) * K + k0 + g * 8, 16);
        }
        cp_commit();
    };

    const int arow = (lane & 7) + (lane & 8);
    const int ahib = (lane & 16) ? 1 : 0;
    const int brow = (lane & 7) + ((lane & 16) ? 8 : 0);
    const int bhib = (lane & 8) ? 1 : 0;
    const int l7   = lane & 7;

    const int nk = K >> 6;
    issue(0, 0);
    if (nk > 1) issue(1, 1);

    for (int i = 0; i < nk; i++) {
        const int buf = i % 3;
        if (i + 1 < nk) cp_wait<1>(); else cp_wait<0>();
        __syncthreads();

        const unsigned aT = sa_s + (unsigned)buf * GSTG;
        const unsigned bT = sb_s + (unsigned)buf * GSTG;
        const unsigned bRow0 = bT + (unsigned)((wn * 32 + brow) * 128);
        const unsigned bRow1 = bT + (unsigned)((wn * 32 + 16 + brow) * 128);

        unsigned bf[2][4][2];
        {
            const unsigned gb = (unsigned)((bhib ^ l7) << 4);
            ldsm_x4(bf[0][0][0], bf[0][0][1], bf[0][1][0], bf[0][1][1], bRow0 + gb);
            ldsm_x4(bf[0][2][0], bf[0][2][1], bf[0][3][0], bf[0][3][1], bRow1 + gb);
        }

        #pragma unroll
        for (int kt = 0; kt < 4; kt++) {
            const int cur = kt & 1;
            if (kt < 3) {
                const unsigned gb = (unsigned)(((2 * (kt + 1) + bhib) ^ l7) << 4);
                ldsm_x4(bf[cur ^ 1][0][0], bf[cur ^ 1][0][1],
                        bf[cur ^ 1][1][0], bf[cur ^ 1][1][1], bRow0 + gb);
                ldsm_x4(bf[cur ^ 1][2][0], bf[cur ^ 1][2][1],
                        bf[cur ^ 1][3][0], bf[cur ^ 1][3][1], bRow1 + gb);
            }
            unsigned af[4][4];
            const unsigned ga = (unsigned)(((2 * kt + ahib) ^ l7) << 4);
            #pragma unroll
            for (int mi = 0; mi < 4; mi++)
                ldsm_x4(af[mi][0], af[mi][1], af[mi][2], af[mi][3],
                        aT + (unsigned)((wm * 64 + mi * 16 + arow) * 128) + ga);
            #pragma unroll
            for (int mi = 0; mi < 4; mi++)
                #pragma unroll
                for (int ni = 0; ni < 4; ni++)
                    mma_f16(acc[mi][ni], af[mi], bf[cur][ni]);
        }

        if (i + 2 < nk) issue(i + 2, (i + 2) % 3);
    }

    // ---- epilogue ----
    #pragma unroll
    for (int mi = 0; mi < 4; mi++) {
        int row1 = m0 + wm * 64 + mi * 16 + r4;
        int row2 = row1 + 8;
        #pragma unroll
        for (int ni = 0; ni < 4; ni++) {
            int colg = n0 + wn * 32 + ni * 8 + c * 2;
            float b0 = s.bias[colg], b1 = s.bias[colg + 1];
            float v00 = acc[mi][ni][0] + b0, v01 = acc[mi][ni][1] + b1;
            float v10 = acc[mi][ni][2] + b0, v11 = acc[mi][ni][3] + b1;
            if (s.otrans) {
                // V segment: store transposed into g_Vt [(b*8+h)*128+dh][SKV_PAD]
                __half* C = (__half*)s.C;
                auto storeT = [&](int m, int d, float v) {
                    if (m < M) {
                        int bb = m / SEQ_KV;
                        int kv = m - bb * SEQ_KV;
                        int hh = d >> 7, dh = d & 127;
                        C[((size_t)(bb * N_HEADS + hh) * D_HEAD + dh) * SKV_PAD + kv] =
                            __float2half_rn(v);
                    }
                };
                storeT(row1, colg,     v00);
                storeT(row1, colg + 1, v01);
                storeT(row2, colg,     v10);
                storeT(row2, colg + 1, v11);
            } else if (s.ohalf) {
                __half* C = (__half*)s.C;
                if (row1 < M)
                    *reinterpret_cast<unsigned*>(C + (size_t)row1 * N + colg) =
                        packh2(s.oscale * v00, s.oscale * v01);
                if (row2 < M)
                    *reinterpret_cast<unsigned*>(C + (size_t)row2 * N + colg) =
                        packh2(s.oscale * v10, s.oscale * v11);
            } else {
                float* C = (float*)s.C;
                if (row1 < M)
                    *reinterpret_cast<float2*>(C + (size_t)row1 * N + colg) = make_float2(v00, v01);
                if (row2 < M)
                    *reinterpret_cast<float2*>(C + (size_t)row2 * N + colg) = make_float2(v10, v11);
            }
        }
    }
}

// ============================================================
// fa9: fp16 flash attention, 2 CTAs/SM, anti-phase chunk stagger.
// CTA: 128 threads (4 warps), 64 q-rows; odd CTAs start at chunk 9
// (mod 17) so co-resident CTAs' softmax/mma phases interleave.
// 3-stage cp.async (96KB), base-2 MUFU softmax, K-frag dbl buffer.
// ============================================================
#define NCHUNK 17
#define KTB 16384u
#define VTB 16384u
#define FA9_SMEM_BYTES (3 * (16384 + 16384))

__global__ __launch_bounds__(128, 2) void fa9_f16(
    const __half* __restrict__ Q, const __half* __restrict__ K,
    const __half* __restrict__ Vt, __half* __restrict__ O)
{
    extern __shared__ unsigned sm4[];

    const int tid  = threadIdx.x;
    const int lane = tid & 31;
    const int wid  = tid >> 5;
    const int r4   = lane >> 2;
    const int c    = lane & 3;
    const int q0   = blockIdx.x * 64;
    const int h    = blockIdx.y;
    const int b    = blockIdx.z;
    const int stag = (blockIdx.x & 1) ? 9 : 0;   // anti-phase offset

    const unsigned sbase = (unsigned)__cvta_generic_to_shared(sm4);
    const unsigned k_s = sbase;
    const unsigned v_s = sbase + 3 * KTB;

    const __half* kb  = K + ((size_t)(b * SEQ_KV)) * D_E + h * D_HEAD;
    const __half* vtb = Vt + ((size_t)(b * N_HEADS + h)) * D_HEAD * SKV_PAD;

    const int lrow = (lane & 7) + ((lane & 16) ? 8 : 0);
    const int kbit = (lane & 8) ? 1 : 0;
    const int lx   = lane & 7;

    unsigned qf[8][4];
    {
        const unsigned* qb = reinterpret_cast<const unsigned*>(
            Q + ((size_t)(b * SEQ_Q + q0 + wid * 16)) * D_E + h * D_HEAD);
        #pragma unroll
        for (int kt = 0; kt < 8; kt++) {
            qf[kt][0] = __ldg(qb + (size_t)r4 * 512 + kt * 8 + c);
            qf[kt][1] = __ldg(qb + (size_t)(r4 + 8) * 512 + kt * 8 + c);
            qf[kt][2] = __ldg(qb + (size_t)r4 * 512 + kt * 8 + c + 4);
            qf[kt][3] = __ldg(qb + (size_t)(r4 + 8) * 512 + kt * 8 + c + 4);
        }
    }

    float oacc[16][4];
    #pragma unroll
    for (int nt = 0; nt < 16; nt++)
        #pragma unroll
        for (int e = 0; e < 4; e++) oacc[nt][e] = 0.0f;

    float row_m0 = -1e30f, row_m1 = -1e30f;
    float row_l0 = 0.0f,   row_l1 = 0.0f;

    auto chunk_of = [&](int t) {
        int ch = t + stag;
        return (ch >= NCHUNK) ? ch - NCHUNK : ch;
    };

    auto issue_chunk = [&](int ch, int buf) {
        const int kv0 = ch * 64;
        #pragma unroll
        for (int i = 0; i < 8; i++) {
            int u = tid + i * 128;
            int kv = u >> 4, g = u & 15;
            int kvg = kv0 + kv;
            int sz = (kvg < SEQ_KV) ? 16 : 0;
            int kvc = (kvg < SEQ_KV) ? kvg : (SEQ_KV - 1);
            cp_async16(k_s + (unsigned)buf * KTB + (unsigned)(kv * 256 + ((g ^ (kv & 7)) << 4)),
                       kb + (size_t)kvc * D_E + g * 8, sz);
        }
        #pragma unroll
        for (int i = 0; i < 8; i++) {
            int u = tid + i * 128;
            int d = u >> 3, g = u & 7;
            cp_async16(v_s + (unsigned)buf * VTB + (unsigned)(d * 128 + ((g ^ (d & 7)) << 4)),
                       vtb + (size_t)d * SKV_PAD + kv0 + g * 8, 16);
        }
        cp_commit();
    };

    issue_chunk(chunk_of(0), 0);
    issue_chunk(chunk_of(1), 1);

    for (int t = 0; t < NCHUNK; t++) {
        const int ch  = chunk_of(t);
        const int kv0 = ch * 64;
        const int buf = t % 3;

        if (t + 1 < NCHUNK) cp_wait<1>(); else cp_wait<0>();
        __syncthreads();

        const unsigned kT = k_s + (unsigned)buf * KTB + lrow * 256;
        const unsigned vT = v_s + (unsigned)buf * VTB + lrow * 128;

        // ---- S = Q @ K^T (log2-domain), K-frags double-buffered ----
        float sacc[8][4];
        #pragma unroll
        for (int ni = 0; ni < 8; ni++)
            #pragma unroll
            for (int e = 0; e < 4; e++) sacc[ni][e] = 0.0f;

        unsigned kf[2][4][4];
        {
            const unsigned g0 = (unsigned)(((kbit) ^ lx) << 4);
            #pragma unroll
            for (int np = 0; np < 4; np++)
                ldsm_x4(kf[0][np][0], kf[0][np][1], kf[0][np][2], kf[0][np][3],
                        kT + np * 4096 + g0);
        }
        #pragma unroll
        for (int kt = 0; kt < 8; kt++) {
            const int cur = kt & 1;
            if (kt < 7) {
                const unsigned gn = (unsigned)(((2 * (kt + 1) + kbit) ^ lx) << 4);
                #pragma unroll
                for (int np = 0; np < 4; np++)
                    ldsm_x4(kf[cur ^ 1][np][0], kf[cur ^ 1][np][1],
                            kf[cur ^ 1][np][2], kf[cur ^ 1][np][3],
                            kT + np * 4096 + gn);
            }
            #pragma unroll
            for (int np = 0; np < 4; np++) {
                unsigned bfA[2] = {kf[cur][np][0], kf[cur][np][1]};
                unsigned bfB[2] = {kf[cur][np][2], kf[cur][np][3]};
                mma_f16(sacc[2 * np],     qf[kt], bfA);
                mma_f16(sacc[2 * np + 1], qf[kt], bfB);
            }
        }

        // ---- base-2 softmax; OOB mask only on the partial chunk ----
        float mx0 = -1e30f, mx1 = -1e30f;
        if (ch == NCHUNK - 1) {
            #pragma unroll
            for (int ni = 0; ni < 8; ni++) {
                int colg = kv0 + ni * 8 + c * 2;
                if (colg >= SEQ_KV) {
                    sacc[ni][0] = -1e30f; sacc[ni][1] = -1e30f;
                    sacc[ni][2] = -1e30f; sacc[ni][3] = -1e30f;
                }
                mx0 = fmaxf(mx0, fmaxf(sacc[ni][0], sacc[ni][1]));
                mx1 = fmaxf(mx1, fmaxf(sacc[ni][2], sacc[ni][3]));
            }
        } else {
            #pragma unroll
            for (int ni = 0; ni < 8; ni++) {
                mx0 = fmaxf(mx0, fmaxf(sacc[ni][0], sacc[ni][1]));
                mx1 = fmaxf(mx1, fmaxf(sacc[ni][2], sacc[ni][3]));
            }
        }
        mx0 = fmaxf(mx0, __shfl_xor_sync(0xffffffffu, mx0, 1));
        mx0 = fmaxf(mx0, __shfl_xor_sync(0xffffffffu, mx0, 2));
        mx1 = fmaxf(mx1, __shfl_xor_sync(0xffffffffu, mx1, 1));
        mx1 = fmaxf(mx1, __shfl_xor_sync(0xffffffffu, mx1, 2));

        float mnew0 = fmaxf(row_m0, mx0);
        float mnew1 = fmaxf(row_m1, mx1);
        float sc0 = fexp2(row_m0 - mnew0);
        float sc1 = fexp2(row_m1 - mnew1);
        row_m0 = mnew0; row_m1 = mnew1;

        float sum0 = 0.f, sum1 = 0.f;
        #pragma unroll
        for (int ni = 0; ni < 8; ni++) {
            sacc[ni][0] = fexp2(sacc[ni][0] - mnew0);
            sacc[ni][1] = fexp2(sacc[ni][1] - mnew0);
            sacc[ni][2] = fexp2(sacc[ni][2] - mnew1);
            sacc[ni][3] = fexp2(sacc[ni][3] - mnew1);
            sum0 += sacc[ni][0] + sacc[ni][1];
            sum1 += sacc[ni][2] + sacc[ni][3];
        }
        sum0 += __shfl_xor_sync(0xffffffffu, sum0, 1);
        sum0 += __shfl_xor_sync(0xffffffffu, sum0, 2);
        sum1 += __shfl_xor_sync(0xffffffffu, sum1, 1);
        sum1 += __shfl_xor_sync(0xffffffffu, sum1, 2);
        row_l0 = row_l0 * sc0 + sum0;
        row_l1 = row_l1 * sc1 + sum1;

        if (!(sc0 == 1.0f && sc1 == 1.0f)) {
            #pragma unroll
            for (int nt = 0; nt < 16; nt++) {
                oacc[nt][0] *= sc0; oacc[nt][1] *= sc0;
                oacc[nt][2] *= sc1; oacc[nt][3] *= sc1;
            }
        }

        // ---- O += P @ V ----
        #pragma unroll
        for (int kt = 0; kt < 4; kt++) {
            unsigned pa[4];
            pa[0] = packh2(sacc[2 * kt][0],     sacc[2 * kt][1]);
            pa[1] = packh2(sacc[2 * kt][2],     sacc[2 * kt][3]);
            pa[2] = packh2(sacc[2 * kt + 1][0], sacc[2 * kt + 1][1]);
            pa[3] = packh2(sacc[2 * kt + 1][2], sacc[2 * kt + 1][3]);

            const unsigned goff = (unsigned)(((2 * kt + kbit) ^ lx) << 4);
            #pragma unroll
            for (int np = 0; np < 8; np++) {
                unsigned b0, b1, b2, b3;
                ldsm_x4(b0, b1, b2, b3, vT + np * 2048 + goff);
                unsigned bfA[2] = {b0, b1};
                unsigned bfB[2] = {b2, b3};
                mma_f16(oacc[2 * np],     pa, bfA);
                mma_f16(oacc[2 * np + 1], pa, bfB);
            }
        }

        if (t + 2 < NCHUNK) issue_chunk(chunk_of(t + 2), (t + 2) % 3);
    }

    float inv0 = 1.0f / row_l0;
    float inv1 = 1.0f / row_l1;
    __half* ob = O + ((size_t)(b * SEQ_Q + q0 + wid * 16 + r4)) * D_E + h * D_HEAD;
    #pragma unroll
    for (int nt = 0; nt < 16; nt++) {
        int colg = nt * 8 + c * 2;
        *reinterpret_cast<unsigned*>(ob + colg) =
            packh2(oacc[nt][0] * inv0, oacc[nt][1] * inv0);
        *reinterpret_cast<unsigned*>(ob + (size_t)8 * D_E + colg) =
            packh2(oacc[nt][2] * inv1, oacc[nt][3] * inv1);
    }
}

// ============================================================
// launch
// ============================================================
extern "C" void kernel_launch(void* const* d_in, const int* in_sizes, int n_in,
                              void* d_out, int out_size)
{
    const float* x  = (const float*)d_in[0];
    const float* y  = (const float*)d_in[1];
    const float* Wq = (const float*)d_in[2];
    const float* bq = (const float*)d_in[3];
    const float* Wk = (const float*)d_in[4];
    const float* bk = (const float*)d_in[5];
    const float* Wv = (const float*)d_in[6];
    const float* bv = (const float*)d_in[7];
    const float* Wo = (const float*)d_in[8];
    const float* bo = (const float*)d_in[9];
    float* out = (float*)d_out;

    __half *hx, *hy, *hWq, *hWk, *hWv, *hWo, *pQ, *pK, *pVt, *pO;
    cudaGetSymbolAddress((void**)&hx,  g_hx);
    cudaGetSymbolAddress((void**)&hy,  g_hy);
    cudaGetSymbolAddress((void**)&hWq, g_hWq);
    cudaGetSymbolAddress((void**)&hWk, g_hWk);
    cudaGetSymbolAddress((void**)&hWv, g_hWv);
    cudaGetSymbolAddress((void**)&hWo, g_hWo);
    cudaGetSymbolAddress((void**)&pQ,  g_Q);
    cudaGetSymbolAddress((void**)&pK,  g_K);
    cudaGetSymbolAddress((void**)&pVt, g_Vt);
    cudaGetSymbolAddress((void**)&pO,  g_O);

    // (1/sqrt(128)) * log2(e): softmax runs in base-2 domain
    const float qscale = 0.08838834764831845f * 1.4426950408889634f;

    // launch 0: all fp32->fp16 conversions
    cvt_all<<<(C_N4 + 255) / 256, 256>>>(x, y, Wq, Wk, Wv, Wo,
                                         hx, hy, hWq, hWk, hWv, hWo);

    cudaFuncSetAttribute(gemm_f16, cudaFuncAttributeMaxDynamicSharedMemorySize, GEMM_SMEM);

    // launch 1: Q + K + V projections in one launch; V written transposed
    Seg sq = { hx, hWq, bq, pQ,  MQ,  D_E, 1, 0, qscale };
    Seg sk = { hy, hWk, bk, pK,  MKV, D_C, 1, 0, 1.0f };
    Seg sv = { hy, hWv, bv, pVt, MKV, D_C, 1, 1, 1.0f };
    gemm_f16<<<dim3(24, (MQ + 127) / 128), 256, GEMM_SMEM>>>(sq, sk, sv, 8, D_E);

    // launch 2: attention (2 CTAs/SM, anti-phase stagger)
    cudaFuncSetAttribute(fa9_f16, cudaFuncAttributeMaxDynamicSharedMemorySize, FA9_SMEM_BYTES);
    fa9_f16<<<dim3(SEQ_Q / 64, N_HEADS, BATCH), 128, FA9_SMEM_BYTES>>>(pQ, pK, pVt, pO);

    // launch 3: output projection -> d_out (fp32)
    Seg so = { pO, hWo, bo, out, MQ, D_E, 0, 0, 1.0f };
    gemm_f16<<<dim3(8, (MQ + 127) / 128), 256, GEMM_SMEM>>>(so, so, so, 8, D_E);
}